// round 16
// baseline (speedup 1.0000x reference)
#include <cuda_runtime.h>
#include <cuda_fp16.h>
#include <cstdint>

// Problem constants (B=64, T=128, N=128, K_SUP=8, E=512, steps=10)
#define M_ROWS   8192          // B*T
#define EDIM     512
#define G4       2048          // 4*E
#define NKS      1024          // N*K_SUP
#define NBATCH   64
#define NSTEPS   10

// ---------------- scratch (device globals; no allocation allowed) ------------
__device__ float g_xW[(size_t)M_ROWS * G4];        // gate-interleaved (c = 4e+gate)
__device__ float g_h[(size_t)M_ROWS * EDIM];
__device__ float g_c[(size_t)M_ROWS * EDIM];
__device__ float g_scores[(size_t)M_ROWS * NKS];
__device__ float g_r[(size_t)M_ROWS * EDIM];
__device__ float g_rmean[(size_t)NBATCH * EDIM];
__device__ float g_bsum[G4];                        // gate-interleaved bias
// fp16 hi/lo split operand buffers
__device__ __half g_hH0[(size_t)M_ROWS * EDIM], g_hL0[(size_t)M_ROWS * EDIM];
__device__ __half g_hH1[(size_t)M_ROWS * EDIM], g_hL1[(size_t)M_ROWS * EDIM];
__device__ __half g_scH[(size_t)M_ROWS * NKS],  g_scL[(size_t)M_ROWS * NKS];
__device__ __half g_tgtH[(size_t)M_ROWS * EDIM], g_tgtL[(size_t)M_ROWS * EDIM];
__device__ __half g_WihH[(size_t)G4 * EDIM],    g_WihL[(size_t)G4 * EDIM];  // interleaved
__device__ __half g_WhhH[(size_t)G4 * EDIM],    g_WhhL[(size_t)G4 * EDIM];  // interleaved
__device__ __half g_supH[(size_t)NBATCH * NKS * EDIM], g_supL[(size_t)NBATCH * NKS * EDIM];
__device__ __half g_supTH[(size_t)NBATCH * EDIM * NKS], g_supTL[(size_t)NBATCH * EDIM * NKS];

// ---------------- fp16 split helpers -----------------------------------------
__device__ __forceinline__ void split2h(float x, __half& hi, __half& lo) {
    hi = __float2half_rn(x);
    lo = __float2half_rn(x - __half2float(hi));
}
__device__ __forceinline__ uint32_t packh(__half a, __half b) {
    __half2 p = __halves2half2(a, b);
    return *(uint32_t*)&p;
}

// elementwise split: float4 -> 4 halves hi + 4 halves lo (uint2 each)
__global__ void split_kernel(const float4* __restrict__ in,
                             uint2* __restrict__ hi, uint2* __restrict__ lo)
{
    long long i = (long long)blockIdx.x * blockDim.x + threadIdx.x;
    float4 v = in[i];
    __half hx, hy, hz, hw, lx, ly, lz, lw;
    split2h(v.x, hx, lx); split2h(v.y, hy, ly);
    split2h(v.z, hz, lz); split2h(v.w, hw, lw);
    hi[i] = make_uint2(packh(hx, hy), packh(hz, hw));
    lo[i] = make_uint2(packh(lx, ly), packh(lz, lw));
}

// W split with gate interleave: new row c <- old row (c&3)*512 + (c>>2)
__global__ void split_W_inter(const float* __restrict__ W,
                              __half* __restrict__ hi, __half* __restrict__ lo)
{
    int f = blockIdx.x * blockDim.x + threadIdx.x;   // float4 id (2048 rows x 128)
    int c  = f >> 7, kq = f & 127;
    int j  = (c & 3) * 512 + (c >> 2);
    float4 v = ((const float4*)W)[(size_t)j * 128 + kq];
    __half hx, hy, hz, hw, lx, ly, lz, lw;
    split2h(v.x, hx, lx); split2h(v.y, hy, ly);
    split2h(v.z, hz, lz); split2h(v.w, hw, lw);
    ((uint2*)hi)[f] = make_uint2(packh(hx, hy), packh(hz, hw));
    ((uint2*)lo)[f] = make_uint2(packh(lx, ly), packh(lz, lw));
}

__global__ void bias_comb(const float* __restrict__ bi, const float* __restrict__ bh,
                          float* __restrict__ bs)
{
    int c = blockIdx.x * blockDim.x + threadIdx.x;
    int j = (c & 3) * 512 + (c >> 2);
    bs[c] = bi[j] + bh[j];
}

// sup[b][n][e] -> supT[b][e][n], split into fp16 hi/lo
__global__ void transpose_split(const float* __restrict__ sup,
                                __half* __restrict__ th, __half* __restrict__ tl)
{
    __shared__ float t[32][33];
    int b = blockIdx.z;
    int e0 = blockIdx.x * 32, n0 = blockIdx.y * 32;
    const float* S = sup + (size_t)b * NKS * EDIM;
    #pragma unroll
    for (int j = 0; j < 4; j++)
        t[threadIdx.y + j * 8][threadIdx.x] =
            S[(size_t)(n0 + threadIdx.y + j * 8) * EDIM + e0 + threadIdx.x];
    __syncthreads();
    __half* TH = th + (size_t)b * EDIM * NKS;
    __half* TL = tl + (size_t)b * EDIM * NKS;
    #pragma unroll
    for (int j = 0; j < 4; j++) {
        float v = t[threadIdx.x][threadIdx.y + j * 8];
        __half h, l; split2h(v, h, l);
        size_t o = (size_t)(e0 + threadIdx.y + j * 8) * NKS + n0 + threadIdx.x;
        TH[o] = h; TL[o] = l;
    }
}

// rmean[b][e] = (1/1024) * sum_{n,k} sup[b][n*k][e]
__global__ void sup_mean(const float* __restrict__ sup, float* __restrict__ rmean)
{
    __shared__ float4 part[128];
    const int b = blockIdx.x;
    const int c4 = threadIdx.x & 127;
    const int half_ = threadIdx.x >> 7;
    const float4* S = (const float4*)(sup + (size_t)b * NKS * EDIM);
    float4 acc = make_float4(0.f, 0.f, 0.f, 0.f);
    for (int n = half_ * 512; n < half_ * 512 + 512; n++) {
        float4 v = S[(size_t)n * 128 + c4];
        acc.x += v.x; acc.y += v.y; acc.z += v.z; acc.w += v.w;
    }
    if (half_) part[c4] = acc;
    __syncthreads();
    if (!half_) {
        float4 o = part[c4];
        const float s = 1.f / 1024.f;
        ((float4*)rmean)[(size_t)b * 128 + c4] = make_float4(
            (acc.x + o.x) * s, (acc.y + o.y) * s, (acc.z + o.z) * s, (acc.w + o.w) * s);
    }
}

// ---------------- 3x-FP16-split NT GEMM, cp.async + ldmatrix ------------------
// C[m,n] = sum_k A[m,k]*B[n,k]; fp16 hi/lo operands (aH*bH + aH*bL + aL*bH),
// fp32 accumulate. Block tile 128x128x32(halves), 128 threads = 4 warps (2x2),
// warp tile 64x64, mma m16n8k16; fragments via ldmatrix.
// EPI=0: C = acc (+Cadd) (+bias) stored.
// EPI=1: fused LSTM cell epilogue (gate-interleaved columns), no C store.
#define BM 128
#define BN 128
#define BKH 32                   // k-depth per tile in halves
#define LDSU 20                  // row stride in u32 (16 data + 4 pad)
#define TILE_U32 (BM * LDSU)     // 2560
#define TILE_B   (TILE_U32 * 4)  // 10240 bytes
#define SMEM_SZ  (8 * TILE_B)    // 81920 bytes -> 2 CTAs/SM
#define GT_LD    132             // epilogue gate-tile row stride (floats)

__device__ __forceinline__ void cpa16(uint32_t dst, const void* src) {
    asm volatile("cp.async.cg.shared.global [%0], [%1], 16;\n"
                 :: "r"(dst), "l"(src));
}
__device__ __forceinline__ void ldsm_x4(uint32_t& r0, uint32_t& r1,
                                        uint32_t& r2, uint32_t& r3, uint32_t a) {
    asm volatile("ldmatrix.sync.aligned.m8n8.x4.shared.b16 {%0,%1,%2,%3}, [%4];"
                 : "=r"(r0), "=r"(r1), "=r"(r2), "=r"(r3) : "r"(a));
}
__device__ __forceinline__ void ldsm_x2(uint32_t& r0, uint32_t& r1, uint32_t a) {
    asm volatile("ldmatrix.sync.aligned.m8n8.x2.shared.b16 {%0,%1}, [%2];"
                 : "=r"(r0), "=r"(r1) : "r"(a));
}

#define MMA_F16(c, a0, a1, a2, a3, b0, b1)                                      \
    asm volatile(                                                               \
        "mma.sync.aligned.m16n8k16.row.col.f32.f16.f16.f32 "                    \
        "{%0,%1,%2,%3}, {%4,%5,%6,%7}, {%8,%9}, {%0,%1,%2,%3};"                 \
        : "+f"((c)[0]), "+f"((c)[1]), "+f"((c)[2]), "+f"((c)[3])                \
        : "r"(a0), "r"(a1), "r"(a2), "r"(a3), "r"(b0), "r"(b1))

template <int EPI>
__global__ __launch_bounds__(128, 2)
void gemm_nt(const __half* __restrict__ AH, const __half* __restrict__ AL,
             const __half* __restrict__ BH, const __half* __restrict__ BL,
             float* __restrict__ C, const float* __restrict__ Cadd,
             const float* __restrict__ bias,
             int N, int K,
             long long aB, long long bB, long long cB,
             const float* __restrict__ xP, const float* __restrict__ rP,
             float* __restrict__ cS, float* __restrict__ hP,
             __half* __restrict__ hHP, __half* __restrict__ hLP)
{
    extern __shared__ uint32_t smem[];
    const uint32_t ubase = (uint32_t)__cvta_generic_to_shared(smem);

    const int tid = threadIdx.x;
    const int bx = blockIdx.x, by = blockIdx.y, bz = blockIdx.z;
    const int lane = tid & 31;
    const int w  = tid >> 5;             // 0..3
    const int wr = w >> 1;               // 0..1 : 64-row half
    const int wc = w & 1;                // 0..1 : 64-col half

    const long long aOff = (long long)bz * aB + (long long)by * BM * K;
    const long long bOff = (long long)bz * bB + (long long)bx * BN * K;
    AH += aOff; AL += aOff; BH += bOff; BL += bOff;
    if (EPI == 0) C += (long long)bz * cB;

    // per-thread cp.async coords: 512 16B-chunks per tile, 4 per thread
    int rr[4], qq[4];
    uint32_t oo[4];
    #pragma unroll
    for (int l = 0; l < 4; l++) {
        int f = tid + l * 128;
        rr[l] = f >> 2; qq[l] = f & 3;
        oo[l] = (uint32_t)(rr[l] * LDSU + qq[l] * 4) * 4;
    }

    auto issue = [&](int stage, int k0) {
        const uint32_t uAH = ubase + stage * TILE_B;
        const uint32_t uAL = ubase + (2 + stage) * TILE_B;
        const uint32_t uBH = ubase + (4 + stage) * TILE_B;
        const uint32_t uBL = ubase + (6 + stage) * TILE_B;
        #pragma unroll
        for (int l = 0; l < 4; l++) {
            long long ga = (long long)rr[l] * K + k0 + qq[l] * 8;
            cpa16(uAH + oo[l], AH + ga);
            cpa16(uAL + oo[l], AL + ga);
            cpa16(uBH + oo[l], BH + ga);
            cpa16(uBL + oo[l], BL + ga);
        }
    };

    // ldmatrix per-lane addresses (bytes within a tile)
    const uint32_t aLn = (uint32_t)(wr * 64 + (lane & 15)) * 80 +
                         ((lane & 16) ? 16u : 0u);
    const uint32_t bLn = (uint32_t)(wc * 64 + (lane & 7)) * 80 +
                         ((lane & 8) ? 16u : 0u);

    float acc[4][8][4];
    #pragma unroll
    for (int i = 0; i < 4; i++)
        #pragma unroll
        for (int j = 0; j < 8; j++)
            #pragma unroll
            for (int q = 0; q < 4; q++) acc[i][j][q] = 0.f;

    const int KT = K / BKH;

    issue(0, 0);
    asm volatile("cp.async.commit_group;\n");

    for (int kt = 0; kt < KT; kt++) {
        asm volatile("cp.async.wait_group 0;\n");
        __syncthreads();

        int pf = kt + 1;
        if (pf < KT) {
            issue(pf & 1, pf * BKH);
            asm volatile("cp.async.commit_group;\n");
        }

        const int stage = kt & 1;
        const uint32_t uAH = ubase + stage * TILE_B + aLn;
        const uint32_t uAL = ubase + (2 + stage) * TILE_B + aLn;
        const uint32_t uBH = ubase + (4 + stage) * TILE_B + bLn;
        const uint32_t uBL = ubase + (6 + stage) * TILE_B + bLn;

        #pragma unroll
        for (int ks = 0; ks < 2; ks++) {          // two k16 sub-steps
            const uint32_t ko = (uint32_t)(ks * 32);
            uint32_t aH[4][4], aL[4][4], bH[8][2], bL[8][2];
            #pragma unroll
            for (int mt = 0; mt < 4; mt++) {
                uint32_t off = (uint32_t)(mt * 1280) + ko;   // 16 rows * 80 B
                ldsm_x4(aH[mt][0], aH[mt][1], aH[mt][2], aH[mt][3], uAH + off);
                ldsm_x4(aL[mt][0], aL[mt][1], aL[mt][2], aL[mt][3], uAL + off);
            }
            #pragma unroll
            for (int nt = 0; nt < 8; nt++) {
                uint32_t off = (uint32_t)(nt * 640) + ko;    // 8 rows * 80 B
                ldsm_x2(bH[nt][0], bH[nt][1], uBH + off);
                ldsm_x2(bL[nt][0], bL[nt][1], uBL + off);
            }
            #pragma unroll
            for (int mt = 0; mt < 4; mt++)
                #pragma unroll
                for (int nt = 0; nt < 8; nt++) {
                    float* c = acc[mt][nt];
                    MMA_F16(c, aH[mt][0], aH[mt][1], aH[mt][2], aH[mt][3],
                            bH[nt][0], bH[nt][1]);
                    MMA_F16(c, aH[mt][0], aH[mt][1], aH[mt][2], aH[mt][3],
                            bL[nt][0], bL[nt][1]);
                    MMA_F16(c, aL[mt][0], aL[mt][1], aL[mt][2], aL[mt][3],
                            bH[nt][0], bH[nt][1]);
                }
        }
    }

    const int eg1 = lane >> 2;
    const int eg2 = lane & 3;

    if (EPI == 0) {
        // ---- epilogue: fp32 adds, float2 stores ----
        const int gr0 = by * BM + wr * 64;
        const int gc0 = bx * BN + wc * 64;
        #pragma unroll
        for (int mt = 0; mt < 4; mt++) {
            #pragma unroll
            for (int nt = 0; nt < 8; nt++) {
                int row = gr0 + mt * 16 + eg1;
                int col = gc0 + nt * 8 + 2 * eg2;
                long long i0 = (long long)row * N + col;
                long long i1 = (long long)(row + 8) * N + col;
                float v0 = acc[mt][nt][0], v1 = acc[mt][nt][1];
                float v2 = acc[mt][nt][2], v3 = acc[mt][nt][3];
                if (Cadd) {
                    float2 u0 = *(const float2*)(Cadd + i0);
                    float2 u1 = *(const float2*)(Cadd + i1);
                    v0 += u0.x; v1 += u0.y; v2 += u1.x; v3 += u1.y;
                }
                if (bias) {
                    float b0 = bias[col], b1 = bias[col + 1];
                    v0 += b0; v1 += b1; v2 += b0; v3 += b1;
                }
                *(float2*)(C + i0) = make_float2(v0, v1);
                *(float2*)(C + i1) = make_float2(v2, v3);
            }
        }
    } else {
        // ---- fused LSTM epilogue (gate-interleaved columns) ----
        __syncthreads();                      // all warps done with tile smem
        float* gt = (float*)smem;             // 128 x GT_LD staging
        #pragma unroll
        for (int mt = 0; mt < 4; mt++) {
            #pragma unroll
            for (int nt = 0; nt < 8; nt++) {
                int rowL = wr * 64 + mt * 16 + eg1;
                int colL = wc * 64 + nt * 8 + 2 * eg2;
                *(float2*)&gt[rowL * GT_LD + colL] =
                    make_float2(acc[mt][nt][0], acc[mt][nt][1]);
                *(float2*)&gt[(rowL + 8) * GT_LD + colL] =
                    make_float2(acc[mt][nt][2], acc[mt][nt][3]);
            }
        }
        __syncthreads();

        const int eL = tid & 31;              // 32 e-values per 128-col tile
        const int mB = (tid >> 5) * 32;       // 4 warps x 32 rows
        const int eG = bx * 32 + eL;
        #pragma unroll 4
        for (int i = 0; i < 32; i++) {
            int mL = mB + i;
            int mG = by * 128 + mL;
            long long idx = (long long)mG * EDIM + eG;
            float4 gv = *(const float4*)&gt[mL * GT_LD + 4 * eL];          // i,f,g,o
            float4 xw = *(const float4*)(Cadd + (long long)mG * G4 + 4 * eG);
            float gi = gv.x + xw.x, gf = gv.y + xw.y;
            float gg = gv.z + xw.z, go = gv.w + xw.w;
            float cp = cS[idx];
            float xv = xP[idx];
            float rv = rP[idx];
            float si = 1.f / (1.f + __expf(-gi));
            float sf = 1.f / (1.f + __expf(-gf));
            float so = 1.f / (1.f + __expf(-go));
            float cn = sf * cp + si * tanhf(gg);
            float hn = so * tanhf(cn) + xv + rv;
            cS[idx] = cn;
            hP[idx] = hn;
            __half hh, hl; split2h(hn, hh, hl);
            hHP[idx] = hh;
            hLP[idx] = hl;
        }
    }
}

// ---------------- softmax over rows of 1024, writes fp16 hi/lo ---------------
__global__ void softmax1024_split(const float* __restrict__ s,
                                  __half* __restrict__ oh, __half* __restrict__ ol)
{
    __shared__ float red[8];
    const float* p = s + (size_t)blockIdx.x * NKS;
    __half* ph = oh + (size_t)blockIdx.x * NKS;
    __half* pl = ol + (size_t)blockIdx.x * NKS;
    const int tid = threadIdx.x;

    float v[4];
    float m = -1e30f;
    #pragma unroll
    for (int i = 0; i < 4; i++) { v[i] = p[tid + i * 256]; m = fmaxf(m, v[i]); }
    #pragma unroll
    for (int o = 16; o > 0; o >>= 1) m = fmaxf(m, __shfl_xor_sync(0xffffffffu, m, o));
    if ((tid & 31) == 0) red[tid >> 5] = m;
    __syncthreads();
    float bm = -1e30f;
    #pragma unroll
    for (int i = 0; i < 8; i++) bm = fmaxf(bm, red[i]);
    __syncthreads();

    float sum = 0.f;
    #pragma unroll
    for (int i = 0; i < 4; i++) { v[i] = __expf(v[i] - bm); sum += v[i]; }
    #pragma unroll
    for (int o = 16; o > 0; o >>= 1) sum += __shfl_xor_sync(0xffffffffu, sum, o);
    if ((tid & 31) == 0) red[tid >> 5] = sum;
    __syncthreads();
    float tot = 0.f;
    #pragma unroll
    for (int i = 0; i < 8; i++) tot += red[i];
    float inv = 1.f / tot;
    #pragma unroll
    for (int i = 0; i < 4; i++) {
        float a = v[i] * inv;
        __half h, l; split2h(a, h, l);
        ph[tid + i * 256] = h;
        pl[tid + i * 256] = l;
    }
}

// step 0: h=c=0 exactly -> gates = xW (interleaved), attn uniform -> r = rmean
__global__ void lstm_pw0(const float* __restrict__ xW, const float* __restrict__ x,
                         const float* __restrict__ rmean, float* __restrict__ h,
                         float* __restrict__ c,
                         __half* __restrict__ hH, __half* __restrict__ hL)
{
    long long idx = (long long)blockIdx.x * blockDim.x + threadIdx.x;
    int m = (int)(idx >> 9);
    int e = (int)(idx & 511);
    int b = m >> 7;
    float4 g = ((const float4*)xW)[(long long)m * 512 + e];   // i,f,g,o interleaved
    float si = 1.f / (1.f + __expf(-g.x));
    float so = 1.f / (1.f + __expf(-g.w));
    float cn = si * tanhf(g.z);
    float hn = so * tanhf(cn) + x[idx] + rmean[(size_t)b * EDIM + e];
    c[idx] = cn;
    h[idx] = hn;
    __half hh, hl; split2h(hn, hh, hl);
    hH[idx] = hh;
    hL[idx] = hl;
}

// ---------------- launch ----------------------------------------------------
extern "C" void kernel_launch(void* const* d_in, const int* in_sizes, int n_in,
                              void* d_out, int out_size)
{
    const float* targets = (const float*)d_in[0];   // [8192, 512]
    const float* sup     = (const float*)d_in[1];   // [64, 1024, 512]
    const float* W_ih    = (const float*)d_in[2];   // [2048, 512]
    const float* W_hh    = (const float*)d_in[3];   // [2048, 512]
    const float* b_ih    = (const float*)d_in[4];   // [2048]
    const float* b_hh    = (const float*)d_in[5];   // [2048]
    float* out = (float*)d_out;

    float *xW, *h, *c, *scores, *r, *rmean, *bsum;
    __half *hH0, *hL0, *hH1, *hL1, *scH, *scL, *tgtH, *tgtL;
    __half *WihH, *WihL, *WhhH, *WhhL, *supH, *supL, *supTH, *supTL;
    cudaGetSymbolAddress((void**)&xW, g_xW);
    cudaGetSymbolAddress((void**)&h, g_h);
    cudaGetSymbolAddress((void**)&c, g_c);
    cudaGetSymbolAddress((void**)&scores, g_scores);
    cudaGetSymbolAddress((void**)&r, g_r);
    cudaGetSymbolAddress((void**)&rmean, g_rmean);
    cudaGetSymbolAddress((void**)&bsum, g_bsum);
    cudaGetSymbolAddress((void**)&hH0, g_hH0);
    cudaGetSymbolAddress((void**)&hL0, g_hL0);
    cudaGetSymbolAddress((void**)&hH1, g_hH1);
    cudaGetSymbolAddress((void**)&hL1, g_hL1);
    cudaGetSymbolAddress((void**)&scH, g_scH);
    cudaGetSymbolAddress((void**)&scL, g_scL);
    cudaGetSymbolAddress((void**)&tgtH, g_tgtH);
    cudaGetSymbolAddress((void**)&tgtL, g_tgtL);
    cudaGetSymbolAddress((void**)&WihH, g_WihH);
    cudaGetSymbolAddress((void**)&WihL, g_WihL);
    cudaGetSymbolAddress((void**)&WhhH, g_WhhH);
    cudaGetSymbolAddress((void**)&WhhL, g_WhhL);
    cudaGetSymbolAddress((void**)&supH, g_supH);
    cudaGetSymbolAddress((void**)&supL, g_supL);
    cudaGetSymbolAddress((void**)&supTH, g_supTH);
    cudaGetSymbolAddress((void**)&supTL, g_supTL);

    cudaFuncSetAttribute(gemm_nt<0>, cudaFuncAttributeMaxDynamicSharedMemorySize, SMEM_SZ);
    cudaFuncSetAttribute(gemm_nt<1>, cudaFuncAttributeMaxDynamicSharedMemorySize, SMEM_SZ);

    dim3 blk(128);

    // one-time operand splits + step-0 mean (W gate-interleaved)
    split_kernel<<<(M_ROWS * EDIM / 4) / 256, 256>>>(
        (const float4*)targets, (uint2*)tgtH, (uint2*)tgtL);
    split_W_inter<<<(G4 * 128) / 256, 256>>>(W_ih, WihH, WihL);
    split_W_inter<<<(G4 * 128) / 256, 256>>>(W_hh, WhhH, WhhL);
    bias_comb<<<G4 / 256, 256>>>(b_ih, b_hh, bsum);
    split_kernel<<<((size_t)NBATCH * NKS * EDIM / 4) / 256, 256>>>(
        (const float4*)sup, (uint2*)supH, (uint2*)supL);
    transpose_split<<<dim3(EDIM / 32, NKS / 32, NBATCH), dim3(32, 8)>>>(
        sup, supTH, supTL);
    sup_mean<<<NBATCH, 256>>>(sup, rmean);

    // xW = x @ W'_ih^T + bsum   (gate-interleaved columns)
    gemm_nt<0><<<dim3(G4 / BN, M_ROWS / BM, 1), blk, SMEM_SZ>>>(
        tgtH, tgtL, WihH, WihL, xW, nullptr, bsum,
        G4, EDIM, 0, 0, 0,
        nullptr, nullptr, nullptr, nullptr, nullptr, nullptr);

    // step 0 fast path (h=0): gates=xW, r=rmean
    lstm_pw0<<<(M_ROWS * EDIM) / 256, 256>>>(xW, targets, rmean, h, c, hH0, hL0);

    for (int s = 1; s < NSTEPS; s++) {
        __half* hHp = (s & 1) ? hH0 : hH1;   // read set (s-1)&1
        __half* hLp = (s & 1) ? hL0 : hL1;
        __half* hHn = (s & 1) ? hH1 : hH0;   // write set s&1
        __half* hLn = (s & 1) ? hL1 : hL0;

        // scores[b] = h_prev[b] @ sup[b]^T   (batched NT)
        gemm_nt<0><<<dim3(NKS / BN, 1, NBATCH), blk, SMEM_SZ>>>(
            hHp, hLp, supH, supL, scores, nullptr, nullptr,
            NKS, EDIM,
            (long long)128 * EDIM, (long long)NKS * EDIM, (long long)128 * NKS,
            nullptr, nullptr, nullptr, nullptr, nullptr, nullptr);

        // softmax -> split attn
        softmax1024_split<<<M_ROWS, 256>>>(scores, scH, scL);

        // r[b] = attn[b] @ supT[b]^T  (NT with B = supT)
        gemm_nt<0><<<dim3(EDIM / BN, 1, NBATCH), blk, SMEM_SZ>>>(
            scH, scL, supTH, supTL, r, nullptr, nullptr,
            EDIM, NKS,
            (long long)128 * NKS, (long long)EDIM * NKS, (long long)128 * EDIM,
            nullptr, nullptr, nullptr, nullptr, nullptr, nullptr);

        // gates = xW + h_prev @ W'_hh^T  with fused LSTM cell epilogue
        gemm_nt<1><<<dim3(G4 / BN, M_ROWS / BM, 1), blk, SMEM_SZ>>>(
            hHp, hLp, WhhH, WhhL, nullptr, xW, nullptr,
            G4, EDIM, 0, 0, 0,
            targets, r, c, h, hHn, hLn);
    }

    cudaMemcpyAsync(out, h, (size_t)M_ROWS * EDIM * sizeof(float),
                    cudaMemcpyDeviceToDevice);
}

// round 17
// speedup vs baseline: 1.2391x; 1.2391x over previous
#include <cuda_runtime.h>
#include <cuda_fp16.h>
#include <cstdint>

// Problem constants (B=64, T=128, N=128, K_SUP=8, E=512, steps=10)
#define M_ROWS   8192          // B*T
#define EDIM     512
#define G4       2048          // 4*E
#define NKS      1024          // N*K_SUP
#define NBATCH   64
#define NSTEPS   10

// ---------------- scratch (device globals; no allocation allowed) ------------
__device__ float g_xW[(size_t)M_ROWS * G4];
__device__ float g_gates[(size_t)M_ROWS * G4];
__device__ float g_h[(size_t)M_ROWS * EDIM];
__device__ float g_c[(size_t)M_ROWS * EDIM];
__device__ float g_scores[(size_t)M_ROWS * NKS];
__device__ float g_r[(size_t)M_ROWS * EDIM];
__device__ float g_rmean[(size_t)NBATCH * EDIM];
// fp16 hi/lo split operand buffers
__device__ __half g_hH[(size_t)M_ROWS * EDIM],  g_hL[(size_t)M_ROWS * EDIM];
__device__ __half g_scH[(size_t)M_ROWS * NKS],  g_scL[(size_t)M_ROWS * NKS];
__device__ __half g_tgtH[(size_t)M_ROWS * EDIM], g_tgtL[(size_t)M_ROWS * EDIM];
__device__ __half g_WihH[(size_t)G4 * EDIM],    g_WihL[(size_t)G4 * EDIM];
__device__ __half g_WhhH[(size_t)G4 * EDIM],    g_WhhL[(size_t)G4 * EDIM];
__device__ __half g_supH[(size_t)NBATCH * NKS * EDIM], g_supL[(size_t)NBATCH * NKS * EDIM];
__device__ __half g_supTH[(size_t)NBATCH * EDIM * NKS], g_supTL[(size_t)NBATCH * EDIM * NKS];

// ---------------- fp16 split helpers -----------------------------------------
__device__ __forceinline__ void split2h(float x, __half& hi, __half& lo) {
    hi = __float2half_rn(x);
    lo = __float2half_rn(x - __half2float(hi));
}
__device__ __forceinline__ uint32_t packh(__half a, __half b) {
    __half2 p = __halves2half2(a, b);
    return *(uint32_t*)&p;
}

// elementwise split: float4 -> 4 halves hi + 4 halves lo (uint2 each)
__global__ void split_kernel(const float4* __restrict__ in,
                             uint2* __restrict__ hi, uint2* __restrict__ lo)
{
    long long i = (long long)blockIdx.x * blockDim.x + threadIdx.x;
    float4 v = in[i];
    __half hx, hy, hz, hw, lx, ly, lz, lw;
    split2h(v.x, hx, lx); split2h(v.y, hy, ly);
    split2h(v.z, hz, lz); split2h(v.w, hw, lw);
    hi[i] = make_uint2(packh(hx, hy), packh(hz, hw));
    lo[i] = make_uint2(packh(lx, ly), packh(lz, lw));
}

// sup[b][n][e] -> supT[b][e][n], split into fp16 hi/lo
__global__ void transpose_split(const float* __restrict__ sup,
                                __half* __restrict__ th, __half* __restrict__ tl)
{
    __shared__ float t[32][33];
    int b = blockIdx.z;
    int e0 = blockIdx.x * 32, n0 = blockIdx.y * 32;
    const float* S = sup + (size_t)b * NKS * EDIM;
    #pragma unroll
    for (int j = 0; j < 4; j++)
        t[threadIdx.y + j * 8][threadIdx.x] =
            S[(size_t)(n0 + threadIdx.y + j * 8) * EDIM + e0 + threadIdx.x];
    __syncthreads();
    __half* TH = th + (size_t)b * EDIM * NKS;
    __half* TL = tl + (size_t)b * EDIM * NKS;
    #pragma unroll
    for (int j = 0; j < 4; j++) {
        float v = t[threadIdx.x][threadIdx.y + j * 8];
        __half h, l; split2h(v, h, l);
        size_t o = (size_t)(e0 + threadIdx.y + j * 8) * NKS + n0 + threadIdx.x;
        TH[o] = h; TL[o] = l;
    }
}

// rmean[b][e] = (1/1024) * sum_{n,k} sup[b][n*k][e]
__global__ void sup_mean(const float* __restrict__ sup, float* __restrict__ rmean)
{
    __shared__ float4 part[128];
    const int b = blockIdx.x;
    const int c4 = threadIdx.x & 127;
    const int half_ = threadIdx.x >> 7;
    const float4* S = (const float4*)(sup + (size_t)b * NKS * EDIM);
    float4 acc = make_float4(0.f, 0.f, 0.f, 0.f);
    for (int n = half_ * 512; n < half_ * 512 + 512; n++) {
        float4 v = S[(size_t)n * 128 + c4];
        acc.x += v.x; acc.y += v.y; acc.z += v.z; acc.w += v.w;
    }
    if (half_) part[c4] = acc;
    __syncthreads();
    if (!half_) {
        float4 o = part[c4];
        const float s = 1.f / 1024.f;
        ((float4*)rmean)[(size_t)b * 128 + c4] = make_float4(
            (acc.x + o.x) * s, (acc.y + o.y) * s, (acc.z + o.z) * s, (acc.w + o.w) * s);
    }
}

// ---------------- 3x-FP16-split NT GEMM, cp.async + ldmatrix ------------------
// Block tile 128x128x32(halves), 128 threads = 4 warps (2x2), warp tile 64x64,
// mma m16n8k16; fragments via ldmatrix. fp32 accumulate.
#define BM 128
#define BN 128
#define BKH 32                   // k-depth per tile in halves
#define LDSU 20                  // row stride in u32 (16 data + 4 pad)
#define TILE_U32 (BM * LDSU)     // 2560
#define TILE_B   (TILE_U32 * 4)  // 10240 bytes
#define SMEM_SZ  (8 * TILE_B)    // 81920 bytes -> 2 CTAs/SM

__device__ __forceinline__ void cpa16(uint32_t dst, const void* src) {
    asm volatile("cp.async.cg.shared.global [%0], [%1], 16;\n"
                 :: "r"(dst), "l"(src));
}
__device__ __forceinline__ void ldsm_x4(uint32_t& r0, uint32_t& r1,
                                        uint32_t& r2, uint32_t& r3, uint32_t a) {
    asm volatile("ldmatrix.sync.aligned.m8n8.x4.shared.b16 {%0,%1,%2,%3}, [%4];"
                 : "=r"(r0), "=r"(r1), "=r"(r2), "=r"(r3) : "r"(a));
}
__device__ __forceinline__ void ldsm_x2(uint32_t& r0, uint32_t& r1, uint32_t a) {
    asm volatile("ldmatrix.sync.aligned.m8n8.x2.shared.b16 {%0,%1}, [%2];"
                 : "=r"(r0), "=r"(r1) : "r"(a));
}

#define MMA_F16(c, a0, a1, a2, a3, b0, b1)                                      \
    asm volatile(                                                               \
        "mma.sync.aligned.m16n8k16.row.col.f32.f16.f16.f32 "                    \
        "{%0,%1,%2,%3}, {%4,%5,%6,%7}, {%8,%9}, {%0,%1,%2,%3};"                 \
        : "+f"((c)[0]), "+f"((c)[1]), "+f"((c)[2]), "+f"((c)[3])                \
        : "r"(a0), "r"(a1), "r"(a2), "r"(a3), "r"(b0), "r"(b1))

// shared mainloop: fills acc[4][8][4] from AH/AL x BH/BL over K halves
__device__ __forceinline__ void gemm_core(
    const __half* AH, const __half* AL, const __half* BH, const __half* BL,
    int K, uint32_t ubase, uint32_t* smem, int tid, int lane, int wr, int wc,
    float acc[4][8][4])
{
    int rr[4], qq[4];
    uint32_t oo[4];
    #pragma unroll
    for (int l = 0; l < 4; l++) {
        int f = tid + l * 128;
        rr[l] = f >> 2; qq[l] = f & 3;
        oo[l] = (uint32_t)(rr[l] * LDSU + qq[l] * 4) * 4;
    }

    auto issue = [&](int stage, int k0) {
        const uint32_t uAH = ubase + stage * TILE_B;
        const uint32_t uAL = ubase + (2 + stage) * TILE_B;
        const uint32_t uBH = ubase + (4 + stage) * TILE_B;
        const uint32_t uBL = ubase + (6 + stage) * TILE_B;
        #pragma unroll
        for (int l = 0; l < 4; l++) {
            long long ga = (long long)rr[l] * K + k0 + qq[l] * 8;
            cpa16(uAH + oo[l], AH + ga);
            cpa16(uAL + oo[l], AL + ga);
            cpa16(uBH + oo[l], BH + ga);
            cpa16(uBL + oo[l], BL + ga);
        }
    };

    const uint32_t aLn = (uint32_t)(wr * 64 + (lane & 15)) * 80 +
                         ((lane & 16) ? 16u : 0u);
    const uint32_t bLn = (uint32_t)(wc * 64 + (lane & 7)) * 80 +
                         ((lane & 8) ? 16u : 0u);

    const int KT = K / BKH;

    issue(0, 0);
    asm volatile("cp.async.commit_group;\n");

    for (int kt = 0; kt < KT; kt++) {
        asm volatile("cp.async.wait_group 0;\n");
        __syncthreads();

        int pf = kt + 1;
        if (pf < KT) {
            issue(pf & 1, pf * BKH);
            asm volatile("cp.async.commit_group;\n");
        }

        const int stage = kt & 1;
        const uint32_t uAH = ubase + stage * TILE_B + aLn;
        const uint32_t uAL = ubase + (2 + stage) * TILE_B + aLn;
        const uint32_t uBH = ubase + (4 + stage) * TILE_B + bLn;
        const uint32_t uBL = ubase + (6 + stage) * TILE_B + bLn;

        #pragma unroll
        for (int ks = 0; ks < 2; ks++) {
            const uint32_t ko = (uint32_t)(ks * 32);
            uint32_t aH[4][4], aL[4][4], bH[8][2], bL[8][2];
            #pragma unroll
            for (int mt = 0; mt < 4; mt++) {
                uint32_t off = (uint32_t)(mt * 1280) + ko;
                ldsm_x4(aH[mt][0], aH[mt][1], aH[mt][2], aH[mt][3], uAH + off);
                ldsm_x4(aL[mt][0], aL[mt][1], aL[mt][2], aL[mt][3], uAL + off);
            }
            #pragma unroll
            for (int nt = 0; nt < 8; nt++) {
                uint32_t off = (uint32_t)(nt * 640) + ko;
                ldsm_x2(bH[nt][0], bH[nt][1], uBH + off);
                ldsm_x2(bL[nt][0], bL[nt][1], uBL + off);
            }
            #pragma unroll
            for (int mt = 0; mt < 4; mt++)
                #pragma unroll
                for (int nt = 0; nt < 8; nt++) {
                    float* c = acc[mt][nt];
                    MMA_F16(c, aH[mt][0], aH[mt][1], aH[mt][2], aH[mt][3],
                            bH[nt][0], bH[nt][1]);
                    MMA_F16(c, aH[mt][0], aH[mt][1], aH[mt][2], aH[mt][3],
                            bL[nt][0], bL[nt][1]);
                    MMA_F16(c, aL[mt][0], aL[mt][1], aL[mt][2], aL[mt][3],
                            bH[nt][0], bH[nt][1]);
                }
        }
    }
}

// general GEMM launch (xW prologue + read GEMM)
__global__ __launch_bounds__(128, 2)
void gemm_nt(const __half* __restrict__ AH, const __half* __restrict__ AL,
             const __half* __restrict__ BH, const __half* __restrict__ BL,
             float* __restrict__ C, const float* __restrict__ Cadd,
             const float* __restrict__ bias1, const float* __restrict__ bias2,
             int N, int K,
             long long aB, long long bB, long long cB)
{
    extern __shared__ uint32_t smem[];
    const uint32_t ubase = (uint32_t)__cvta_generic_to_shared(smem);
    const int tid = threadIdx.x;
    const int bx = blockIdx.x, by = blockIdx.y, bz = blockIdx.z;
    const int lane = tid & 31;
    const int w  = tid >> 5;
    const int wr = w >> 1;
    const int wc = w & 1;

    const long long aOff = (long long)bz * aB + (long long)by * BM * K;
    const long long bOff = (long long)bz * bB + (long long)bx * BN * K;
    AH += aOff; AL += aOff; BH += bOff; BL += bOff;
    C += (long long)bz * cB;

    float acc[4][8][4];
    #pragma unroll
    for (int i = 0; i < 4; i++)
        #pragma unroll
        for (int j = 0; j < 8; j++)
            #pragma unroll
            for (int q = 0; q < 4; q++) acc[i][j][q] = 0.f;

    gemm_core(AH, AL, BH, BL, K, ubase, smem, tid, lane, wr, wc, acc);

    const int eg1 = lane >> 2;
    const int eg2 = lane & 3;
    const int gr0 = by * BM + wr * 64;
    const int gc0 = bx * BN + wc * 64;
    #pragma unroll
    for (int mt = 0; mt < 4; mt++) {
        #pragma unroll
        for (int nt = 0; nt < 8; nt++) {
            int row = gr0 + mt * 16 + eg1;
            int col = gc0 + nt * 8 + 2 * eg2;
            long long i0 = (long long)row * N + col;
            long long i1 = (long long)(row + 8) * N + col;
            float v0 = acc[mt][nt][0], v1 = acc[mt][nt][1];
            float v2 = acc[mt][nt][2], v3 = acc[mt][nt][3];
            if (Cadd) {
                float2 u0 = *(const float2*)(Cadd + i0);
                float2 u1 = *(const float2*)(Cadd + i1);
                v0 += u0.x; v1 += u0.y; v2 += u1.x; v3 += u1.y;
            }
            if (bias1) {
                float bb0 = bias1[col] + bias2[col];
                float bb1 = bias1[col + 1] + bias2[col + 1];
                v0 += bb0; v1 += bb1; v2 += bb0; v3 += bb1;
            }
            *(float2*)(C + i0) = make_float2(v0, v1);
            *(float2*)(C + i1) = make_float2(v2, v3);
        }
    }
}

// merged per-step launch: gates GEMM (1024 CTAs) + scores GEMM (512 CTAs)
// id < 1024: gates tile  (bx=id&15 col-block of 2048, blk=id>>4 row-block of h)
// id >= 1024: scores tile (bx=j&7 col-block of 1024, blk=j>>3 batch)
__global__ __launch_bounds__(128, 2)
void gemm_merged(const __half* __restrict__ hH, const __half* __restrict__ hL,
                 const __half* __restrict__ WhhH, const __half* __restrict__ WhhL,
                 const __half* __restrict__ supH, const __half* __restrict__ supL,
                 float* __restrict__ gates, const float* __restrict__ xW,
                 float* __restrict__ scores)
{
    extern __shared__ uint32_t smem[];
    const uint32_t ubase = (uint32_t)__cvta_generic_to_shared(smem);
    const int tid = threadIdx.x;
    const int lane = tid & 31;
    const int w  = tid >> 5;
    const int wr = w >> 1;
    const int wc = w & 1;

    const int id = blockIdx.x;
    const __half *AH, *AL, *BH, *BL;
    float* C;
    const float* Cadd;
    int N, rowOff, colOff;
    if (id < 1024) {                      // gates = xW + h @ Whh'^T
        int bx = id & 15, blk = id >> 4;
        AH = hH + (size_t)blk * (128 * EDIM);
        AL = hL + (size_t)blk * (128 * EDIM);
        BH = WhhH + (size_t)bx * (128 * EDIM);
        BL = WhhL + (size_t)bx * (128 * EDIM);
        C = gates; Cadd = xW; N = G4;
        rowOff = blk * 128; colOff = bx * 128;
    } else {                              // scores[b] = h[b] @ sup[b]^T
        int j = id - 1024;
        int bx = j & 7, blk = j >> 3;
        AH = hH + (size_t)blk * (128 * EDIM);
        AL = hL + (size_t)blk * (128 * EDIM);
        BH = supH + (size_t)blk * (NKS * EDIM) + (size_t)bx * (128 * EDIM);
        BL = supL + (size_t)blk * (NKS * EDIM) + (size_t)bx * (128 * EDIM);
        C = scores + (size_t)blk * (128 * NKS); Cadd = nullptr; N = NKS;
        rowOff = 0; colOff = bx * 128;
    }

    float acc[4][8][4];
    #pragma unroll
    for (int i = 0; i < 4; i++)
        #pragma unroll
        for (int j = 0; j < 8; j++)
            #pragma unroll
            for (int q = 0; q < 4; q++) acc[i][j][q] = 0.f;

    gemm_core(AH, AL, BH, BL, EDIM, ubase, smem, tid, lane, wr, wc, acc);

    const int eg1 = lane >> 2;
    const int eg2 = lane & 3;
    const int gr0 = rowOff + wr * 64;
    const int gc0 = colOff + wc * 64;
    #pragma unroll
    for (int mt = 0; mt < 4; mt++) {
        #pragma unroll
        for (int nt = 0; nt < 8; nt++) {
            int row = gr0 + mt * 16 + eg1;
            int col = gc0 + nt * 8 + 2 * eg2;
            long long i0 = (long long)row * N + col;
            long long i1 = (long long)(row + 8) * N + col;
            float v0 = acc[mt][nt][0], v1 = acc[mt][nt][1];
            float v2 = acc[mt][nt][2], v3 = acc[mt][nt][3];
            if (Cadd) {
                float2 u0 = *(const float2*)(Cadd + i0);
                float2 u1 = *(const float2*)(Cadd + i1);
                v0 += u0.x; v1 += u0.y; v2 += u1.x; v3 += u1.y;
            }
            *(float2*)(C + i0) = make_float2(v0, v1);
            *(float2*)(C + i1) = make_float2(v2, v3);
        }
    }
}

// ---------------- softmax over rows of 1024, writes fp16 hi/lo ---------------
__global__ void softmax1024_split(const float* __restrict__ s,
                                  __half* __restrict__ oh, __half* __restrict__ ol)
{
    __shared__ float red[8];
    const float* p = s + (size_t)blockIdx.x * NKS;
    __half* ph = oh + (size_t)blockIdx.x * NKS;
    __half* pl = ol + (size_t)blockIdx.x * NKS;
    const int tid = threadIdx.x;

    float v[4];
    float m = -1e30f;
    #pragma unroll
    for (int i = 0; i < 4; i++) { v[i] = p[tid + i * 256]; m = fmaxf(m, v[i]); }
    #pragma unroll
    for (int o = 16; o > 0; o >>= 1) m = fmaxf(m, __shfl_xor_sync(0xffffffffu, m, o));
    if ((tid & 31) == 0) red[tid >> 5] = m;
    __syncthreads();
    float bm = -1e30f;
    #pragma unroll
    for (int i = 0; i < 8; i++) bm = fmaxf(bm, red[i]);
    __syncthreads();

    float sum = 0.f;
    #pragma unroll
    for (int i = 0; i < 4; i++) { v[i] = __expf(v[i] - bm); sum += v[i]; }
    #pragma unroll
    for (int o = 16; o > 0; o >>= 1) sum += __shfl_xor_sync(0xffffffffu, sum, o);
    if ((tid & 31) == 0) red[tid >> 5] = sum;
    __syncthreads();
    float tot = 0.f;
    #pragma unroll
    for (int i = 0; i < 8; i++) tot += red[i];
    float inv = 1.f / tot;
    #pragma unroll
    for (int i = 0; i < 4; i++) {
        float a = v[i] * inv;
        __half h, l; split2h(a, h, l);
        ph[tid + i * 256] = h;
        pl[tid + i * 256] = l;
    }
}

// ---------------- fused LSTM pointwise (writes h + fp16 split) ---------------
__global__ void lstm_pw(const float* __restrict__ gates, const float* __restrict__ x,
                        const float* __restrict__ r, float* __restrict__ h,
                        float* __restrict__ c,
                        __half* __restrict__ hH, __half* __restrict__ hL)
{
    long long idx = (long long)blockIdx.x * blockDim.x + threadIdx.x;
    int m = (int)(idx >> 9);
    int e = (int)(idx & 511);
    const float* grow = gates + (long long)m * G4;
    float gi = grow[e];
    float gf = grow[512 + e];
    float gg = grow[1024 + e];
    float go = grow[1536 + e];
    float cp = c[idx];
    float si = 1.f / (1.f + __expf(-gi));
    float sf = 1.f / (1.f + __expf(-gf));
    float so = 1.f / (1.f + __expf(-go));
    float cn = sf * cp + si * tanhf(gg);
    float hn = so * tanhf(cn) + x[idx] + r[idx];
    c[idx] = cn;
    h[idx] = hn;
    __half hh, hl; split2h(hn, hh, hl);
    hH[idx] = hh;
    hL[idx] = hl;
}

// step 0: h=c=0 exactly -> gates = xW, attn uniform -> r = rmean[b]
__global__ void lstm_pw0(const float* __restrict__ xW, const float* __restrict__ x,
                         const float* __restrict__ rmean, float* __restrict__ h,
                         float* __restrict__ c,
                         __half* __restrict__ hH, __half* __restrict__ hL)
{
    long long idx = (long long)blockIdx.x * blockDim.x + threadIdx.x;
    int m = (int)(idx >> 9);
    int e = (int)(idx & 511);
    int b = m >> 7;
    const float* grow = xW + (long long)m * G4;
    float gi = grow[e];
    float gg = grow[1024 + e];
    float go = grow[1536 + e];
    float si = 1.f / (1.f + __expf(-gi));
    float so = 1.f / (1.f + __expf(-go));
    float cn = si * tanhf(gg);
    float hn = so * tanhf(cn) + x[idx] + rmean[(size_t)b * EDIM + e];
    c[idx] = cn;
    h[idx] = hn;
    __half hh, hl; split2h(hn, hh, hl);
    hH[idx] = hh;
    hL[idx] = hl;
}

// ---------------- launch ----------------------------------------------------
extern "C" void kernel_launch(void* const* d_in, const int* in_sizes, int n_in,
                              void* d_out, int out_size)
{
    const float* targets = (const float*)d_in[0];   // [8192, 512]
    const float* sup     = (const float*)d_in[1];   // [64, 1024, 512]
    const float* W_ih    = (const float*)d_in[2];   // [2048, 512]
    const float* W_hh    = (const float*)d_in[3];   // [2048, 512]
    const float* b_ih    = (const float*)d_in[4];   // [2048]
    const float* b_hh    = (const float*)d_in[5];   // [2048]
    float* out = (float*)d_out;

    float *xW, *gates, *h, *c, *scores, *r, *rmean;
    __half *hH, *hL, *scH, *scL, *tgtH, *tgtL;
    __half *WihH, *WihL, *WhhH, *WhhL, *supH, *supL, *supTH, *supTL;
    cudaGetSymbolAddress((void**)&xW, g_xW);
    cudaGetSymbolAddress((void**)&gates, g_gates);
    cudaGetSymbolAddress((void**)&h, g_h);
    cudaGetSymbolAddress((void**)&c, g_c);
    cudaGetSymbolAddress((void**)&scores, g_scores);
    cudaGetSymbolAddress((void**)&r, g_r);
    cudaGetSymbolAddress((void**)&rmean, g_rmean);
    cudaGetSymbolAddress((void**)&hH, g_hH);
    cudaGetSymbolAddress((void**)&hL, g_hL);
    cudaGetSymbolAddress((void**)&scH, g_scH);
    cudaGetSymbolAddress((void**)&scL, g_scL);
    cudaGetSymbolAddress((void**)&tgtH, g_tgtH);
    cudaGetSymbolAddress((void**)&tgtL, g_tgtL);
    cudaGetSymbolAddress((void**)&WihH, g_WihH);
    cudaGetSymbolAddress((void**)&WihL, g_WihL);
    cudaGetSymbolAddress((void**)&WhhH, g_WhhH);
    cudaGetSymbolAddress((void**)&WhhL, g_WhhL);
    cudaGetSymbolAddress((void**)&supH, g_supH);
    cudaGetSymbolAddress((void**)&supL, g_supL);
    cudaGetSymbolAddress((void**)&supTH, g_supTH);
    cudaGetSymbolAddress((void**)&supTL, g_supTL);

    cudaFuncSetAttribute(gemm_nt, cudaFuncAttributeMaxDynamicSharedMemorySize, SMEM_SZ);
    cudaFuncSetAttribute(gemm_merged, cudaFuncAttributeMaxDynamicSharedMemorySize, SMEM_SZ);

    dim3 blk(128);

    // one-time operand splits + step-0 mean
    split_kernel<<<(M_ROWS * EDIM / 4) / 256, 256>>>(
        (const float4*)targets, (uint2*)tgtH, (uint2*)tgtL);
    split_kernel<<<(G4 * EDIM / 4) / 256, 256>>>(
        (const float4*)W_ih, (uint2*)WihH, (uint2*)WihL);
    split_kernel<<<(G4 * EDIM / 4) / 256, 256>>>(
        (const float4*)W_hh, (uint2*)WhhH, (uint2*)WhhL);
    split_kernel<<<((size_t)NBATCH * NKS * EDIM / 4) / 256, 256>>>(
        (const float4*)sup, (uint2*)supH, (uint2*)supL);
    transpose_split<<<dim3(EDIM / 32, NKS / 32, NBATCH), dim3(32, 8)>>>(
        sup, supTH, supTL);
    sup_mean<<<NBATCH, 256>>>(sup, rmean);

    // xW = x @ W_ih^T + b_ih + b_hh   (loop-invariant)
    gemm_nt<<<dim3(G4 / BN, M_ROWS / BM, 1), blk, SMEM_SZ>>>(
        tgtH, tgtL, WihH, WihL, xW, nullptr, b_ih, b_hh,
        G4, EDIM, 0, 0, 0);

    // step 0 fast path (h=0): gates=xW, r=rmean
    lstm_pw0<<<(M_ROWS * EDIM) / 256, 256>>>(xW, targets, rmean, h, c, hH, hL);

    for (int s = 1; s < NSTEPS; s++) {
        // gates = xW + h @ Whh^T  AND  scores[b] = h[b] @ sup[b]^T  (one launch)
        gemm_merged<<<1536, blk, SMEM_SZ>>>(
            hH, hL, WhhH, WhhL, supH, supL, gates, xW, scores);

        // softmax -> split attn
        softmax1024_split<<<M_ROWS, 256>>>(scores, scH, scL);

        // r[b] = attn[b] @ supT[b]^T  (NT with B = supT)
        gemm_nt<<<dim3(EDIM / BN, 1, NBATCH), blk, SMEM_SZ>>>(
            scH, scL, supTH, supTL, r, nullptr, nullptr, nullptr,
            EDIM, NKS,
            (long long)128 * NKS, (long long)EDIM * NKS, (long long)128 * EDIM);

        // pointwise LSTM cell + residual adds (+ h split for next step)
        lstm_pw<<<(M_ROWS * EDIM) / 256, 256>>>(gates, targets, r, h, c, hH, hL);
    }

    cudaMemcpyAsync(out, h, (size_t)M_ROWS * EDIM * sizeof(float),
                    cudaMemcpyDeviceToDevice);
}